// round 16
// baseline (speedup 1.0000x reference)
#include <cuda_runtime.h>
#include <math.h>

// ---------------- problem constants (fixed by the dataset) ----------------
#define NN      102400      // B*S*M nodes
#define EE      3276800     // edges
#define FF      256         // input features
#define DTOT    97          // concat latent dim
#define BGR     64          // graphs
#define SSUB    32          // subgraphs per graph
#define MM      50          // nodes per subgraph
#define KTOP    30          // sort-pool k
#define C1      16
#define C2      32
#define L1IN    352
#define HID     128
#define NCLS    10

typedef unsigned long long ull;
__device__ __forceinline__ ull dup2(float a) {
    ull r; asm("mov.b64 %0,{%1,%1};" : "=l"(r) : "f"(a)); return r;
}
__device__ __forceinline__ ull fma2(ull a, ull b, ull c) {
    ull d; asm("fma.rn.f32x2 %0,%1,%2,%3;" : "=l"(d) : "l"(a), "l"(b), "l"(c)); return d;
}
__device__ __forceinline__ void upk(ull v, float& lo, float& hi) {
    asm("mov.b64 {%0,%1},%2;" : "=f"(lo), "=f"(hi) : "l"(v));
}

// ---------------- device scratch (static, no allocation) ------------------
// NOTE: never pass these symbols as kernel arguments from host code — that
// passes the host shadow address (silently readable-as-zeros on GB300 ATS).
// d_deg invariant: all-zeros at kernel_launch entry (module-load zeros it;
// k_fill's atomicSub cursor returns it to zero every call).
__device__ int   d_deg[NN];
__device__ float d_dinv[NN];
__device__ int   d_off[NN + 1];
__device__ int   d_csr[EE];
__device__ float d_Ga[NN * 32];
__device__ float d_Gb[NN * 32];
__device__ float d_G1[NN];           // layer-3 gemv output
__device__ float d_cs[NN * DTOT];    // concatenated states
__device__ float d_feat[BGR * SSUB * L1IN];
__device__ float d_h3[BGR * SSUB * HID];

// ---------------- preprocessing --------------------------------------------
// int4-vectorized: 4 edges per thread, 4 atomics in flight behind 1 LDG.128.
__global__ void k_degree(const int* __restrict__ eidx) {
    int e4 = blockIdx.x * blockDim.x + threadIdx.x;
    if (e4 < EE / 4) {
        int4 c = ((const int4*)(eidx + EE))[e4];
        atomicAdd(&d_deg[c.x], 1);
        atomicAdd(&d_deg[c.y], 1);
        atomicAdd(&d_deg[c.z], 1);
        atomicAdd(&d_deg[c.w], 1);
    }
}

// single-block coalesced scan: 100 tiles x 1024, warp-shuffle based.
// computes offsets + dinv. deg is left intact (k_fill consumes it to zero).
__global__ __launch_bounds__(1024) void k_scan() {
    __shared__ int wsum[32];
    int t = threadIdx.x, lane = t & 31, wid = t >> 5;
    int carry = 0;
    for (int tile = 0; tile < NN / 1024; tile++) {
        int idx = tile * 1024 + t;
        int v = d_deg[idx];
        int x = v;
        #pragma unroll
        for (int o = 1; o < 32; o <<= 1) {
            int y = __shfl_up_sync(0xffffffffu, x, o);
            if (lane >= o) x += y;
        }
        if (lane == 31) wsum[wid] = x;
        __syncthreads();
        if (wid == 0) {
            int s = wsum[lane];
            #pragma unroll
            for (int o = 1; o < 32; o <<= 1) {
                int y = __shfl_up_sync(0xffffffffu, s, o);
                if (lane >= o) s += y;
            }
            wsum[lane] = s;
        }
        __syncthreads();
        int off = carry + (wid ? wsum[wid - 1] : 0) + x - v;
        d_off[idx] = off;
        d_dinv[idx] = rsqrtf((float)(v + 1));  // +1 self loop
        carry += wsum[31];
        __syncthreads();
    }
    if (t == 1023) d_off[NN] = carry;
}

// fill with DOWN-counting cursor (int4: 4 edges per thread): after this
// kernel d_deg == 0 everywhere, restoring the entry invariant.
__global__ void k_fill(const int* __restrict__ eidx) {
    int e4 = blockIdx.x * blockDim.x + threadIdx.x;
    if (e4 < EE / 4) {
        int4 c = ((const int4*)(eidx + EE))[e4];
        int4 r = ((const int4*)eidx)[e4];
        int p0 = d_off[c.x] + atomicSub(&d_deg[c.x], 1) - 1;
        int p1 = d_off[c.y] + atomicSub(&d_deg[c.y], 1) - 1;
        int p2 = d_off[c.z] + atomicSub(&d_deg[c.z], 1) - 1;
        int p3 = d_off[c.w] + atomicSub(&d_deg[c.w], 1) - 1;
        d_csr[p0] = r.x;
        d_csr[p1] = r.y;
        d_csr[p2] = r.z;
        d_csr[p3] = r.w;
    }
}

// ---------------- GEMM layer 0: Ga = dinv * (x[N,256] @ W0[256,32]) --------
// 64 threads, tile 128 rows x 32 cols, per-thread 8 rows x 8 cols
// (best measured config: 52.0us). Packed fma.rn.f32x2 on row pairs;
// Xs transposed [kk][row] pitch 138 + 2-float skew per 32-row group;
// W cached in two 128-k halves (16KB). smem 33.7KB.
// per-accumulator k-order: k ascending 0..255 (identical numerics).
#define XPITCH 138
#define XIDX(kk, row) ((kk) * XPITCH + (row) + ((((row) >> 5)) << 1))
__global__ __launch_bounds__(64) void k_gemm0(const float* __restrict__ X,
                                              const float* __restrict__ W) {
    __shared__ float Ws[128 * 32];       // 16 KB: half of W ([kk][col])
    __shared__ float Xs[32 * XPITCH];    // 17.7 KB: [kk][row], skewed
    int tid = threadIdx.x;
    int node0 = blockIdx.x * 128;

    int ty = tid >> 2;       // 0..15 -> rows ty*8 .. ty*8+7
    int tx = tid & 3;        // cols tx*8 .. tx*8+7
    int xbase = ty * 8 + ((ty >> 2) << 1);   // skewed row base (const/thread)

    ull acc2[4][8];          // [row-pair][col]
    #pragma unroll
    for (int u = 0; u < 4; u++)
        #pragma unroll
        for (int c = 0; c < 8; c++) acc2[u][c] = 0ull;

    int q  = tid & 7;        // loader kk group: kk q*4..q*4+3
    int rr = tid >> 3;       // loader row residue 0..7

    for (int kh = 0; kh < 2; kh++) {
        __syncthreads();     // all compute on previous Ws done
        for (int i = tid; i < 1024; i += 64)
            ((float4*)Ws)[i] = ((const float4*)W)[kh * 1024 + i];
        for (int kt = 0; kt < 4; kt++) {
            __syncthreads();
            #pragma unroll
            for (int p = 0; p < 16; p++) {
                int row = p * 8 + rr;                // rows 0..127, each once
                float4 v = *(const float4*)
                    &X[(node0 + row) * FF + kh * 128 + kt * 32 + q * 4];
                Xs[XIDX(q * 4 + 0, row)] = v.x;
                Xs[XIDX(q * 4 + 1, row)] = v.y;
                Xs[XIDX(q * 4 + 2, row)] = v.z;
                Xs[XIDX(q * 4 + 3, row)] = v.w;
            }
            __syncthreads();
            #pragma unroll 8
            for (int kk = 0; kk < 32; kk++) {
                const float* wrow = &Ws[(kt * 32 + kk) * 32 + tx * 8];
                float4 w0 = *(const float4*)wrow;
                float4 w1 = *(const float4*)(wrow + 4);
                ull wd[8] = {dup2(w0.x), dup2(w0.y), dup2(w0.z), dup2(w0.w),
                             dup2(w1.x), dup2(w1.y), dup2(w1.z), dup2(w1.w)};
                const float* xrow = &Xs[kk * XPITCH + xbase];
                ull xp[4];
                xp[0] = *(const ull*)(xrow + 0);
                xp[1] = *(const ull*)(xrow + 2);
                xp[2] = *(const ull*)(xrow + 4);
                xp[3] = *(const ull*)(xrow + 6);
                #pragma unroll
                for (int u = 0; u < 4; u++)
                    #pragma unroll
                    for (int c = 0; c < 8; c++)
                        acc2[u][c] = fma2(xp[u], wd[c], acc2[u][c]);
            }
        }
    }
    #pragma unroll
    for (int u = 0; u < 4; u++) {
        int n0 = node0 + ty * 8 + 2 * u;
        float dv0 = d_dinv[n0], dv1 = d_dinv[n0 + 1];
        float lo[8], hi[8];
        #pragma unroll
        for (int c = 0; c < 8; c++) upk(acc2[u][c], lo[c], hi[c]);
        float4 a0 = {lo[0] * dv0, lo[1] * dv0, lo[2] * dv0, lo[3] * dv0};
        float4 a1 = {lo[4] * dv0, lo[5] * dv0, lo[6] * dv0, lo[7] * dv0};
        float4 b0 = {hi[0] * dv1, hi[1] * dv1, hi[2] * dv1, hi[3] * dv1};
        float4 b1 = {hi[4] * dv1, hi[5] * dv1, hi[6] * dv1, hi[7] * dv1};
        *(float4*)&d_Ga[n0 * 32 + tx * 8]           = a0;
        *(float4*)&d_Ga[n0 * 32 + tx * 8 + 4]       = a1;
        *(float4*)&d_Ga[(n0 + 1) * 32 + tx * 8]     = b0;
        *(float4*)&d_Ga[(n0 + 1) * 32 + tx * 8 + 4] = b1;
    }
}

// ---------------- vectorized gather: 4 neighbors per warp-instruction ------
// lane = g*8 + sub: group g (0..3) owns neighbors j = jj*4+g, sub (0..7)
// owns channel quad sub*4..sub*4+3. Per 4 edges: 1 SHFL + 1 LDG.128 + 4 FADD.
__device__ __forceinline__ float gather_row(const float* __restrict__ Gin,
                                            int warp, int lane) {
    const float4* __restrict__ Gin4 = (const float4*)Gin;
    int g = lane >> 3;
    int sub = lane & 7;
    float4 acc = make_float4(0.f, 0.f, 0.f, 0.f);
    if (g == 0) acc = __ldg(&Gin4[warp * 8 + sub]);     // self loop
    int s = d_off[warp], e = d_off[warp + 1];
    for (int base = s; base < e; base += 32) {
        int idx = base + lane;
        int src = (idx < e) ? d_csr[idx] : 0;
        int cnt = min(32, e - base);
        #pragma unroll
        for (int jj = 0; jj < 8; jj++) {
            if (jj * 4 >= cnt) break;                   // warp-uniform
            int j = jj * 4 + g;
            int sj = __shfl_sync(0xffffffffu, src, j);
            if (j < cnt) {
                float4 v = __ldg(&Gin4[sj * 8 + sub]);
                acc.x += v.x; acc.y += v.y; acc.z += v.z; acc.w += v.w;
            }
        }
    }
    // combine partial sums across the 4 groups (same sub)
    acc.x += __shfl_xor_sync(0xffffffffu, acc.x, 8);
    acc.y += __shfl_xor_sync(0xffffffffu, acc.y, 8);
    acc.z += __shfl_xor_sync(0xffffffffu, acc.z, 8);
    acc.w += __shfl_xor_sync(0xffffffffu, acc.w, 8);
    acc.x += __shfl_xor_sync(0xffffffffu, acc.x, 16);
    acc.y += __shfl_xor_sync(0xffffffffu, acc.y, 16);
    acc.z += __shfl_xor_sync(0xffffffffu, acc.z, 16);
    acc.w += __shfl_xor_sync(0xffffffffu, acc.w, 16);
    // redistribute: lane k takes component k&3 from lane k>>2 (sub = k>>2)
    int srcl = lane >> 2;
    float c0 = __shfl_sync(0xffffffffu, acc.x, srcl);
    float c1 = __shfl_sync(0xffffffffu, acc.y, srcl);
    float c2 = __shfl_sync(0xffffffffu, acc.z, srcl);
    float c3 = __shfl_sync(0xffffffffu, acc.w, srcl);
    int r = lane & 3;
    return (r == 0) ? c0 : (r == 1) ? c1 : (r == 2) ? c2 : c3;
}

// ---------------- fused aggregation + next-layer 32x32 GEMM ----------------
// ab=0: Gin=d_Ga, Gout=d_Gb;  ab=1: Gin=d_Gb, Gout=d_Ga (device-side select).
__global__ __launch_bounds__(256) void k_aggF(const float* __restrict__ b,
                                              int colOff, int ab,
                                              const float* __restrict__ Wn) {
    const float* __restrict__ Gin = ab ? d_Gb : d_Ga;
    float* __restrict__ Gout = ab ? d_Ga : d_Gb;
    __shared__ float Ws[1024];
    int tid = threadIdx.x;
    if (tid < 256) ((float4*)Ws)[tid] = ((const float4*)Wn)[tid];
    __syncthreads();

    int warp = (blockIdx.x * 256 + tid) >> 5;
    int lane = tid & 31;
    float acc = gather_row(Gin, warp, lane);
    float dv = d_dinv[warp];
    float v = tanhf(dv * acc + b[lane]);
    d_cs[warp * DTOT + colOff + lane] = v;
    float g = 0.f;
    #pragma unroll
    for (int k = 0; k < 32; k++) {
        float vk = __shfl_sync(0xffffffffu, v, k);
        g = fmaf(vk, Ws[k * 32 + lane], g);
    }
    Gout[warp * 32 + lane] = g * dv;
}

// layer-2 variant: fused agg (Gin = d_Ga) + gemv(32->1) -> d_G1
__global__ __launch_bounds__(256) void k_aggF2(const float* __restrict__ b,
                                               const float* __restrict__ W3) {
    int tid = threadIdx.x;
    int warp = (blockIdx.x * 256 + tid) >> 5;
    int lane = tid & 31;
    float acc = gather_row(d_Ga, warp, lane);
    float dv = d_dinv[warp];
    float v = tanhf(dv * acc + b[lane]);
    d_cs[warp * DTOT + 64 + lane] = v;
    float t = v * __ldg(&W3[lane]);
    #pragma unroll
    for (int o = 16; o; o >>= 1) t += __shfl_xor_sync(0xffffffffu, t, o);
    if (lane == 0) d_G1[warp] = t * dv;
}

__global__ __launch_bounds__(256) void k_agg1(const float* __restrict__ b3) {
    int node = (blockIdx.x * blockDim.x + threadIdx.x) >> 5;
    int lane = threadIdx.x & 31;
    int s = d_off[node], e = d_off[node + 1];
    float acc = 0.f;
    for (int idx = s + lane; idx < e; idx += 32)
        acc += __ldg(&d_G1[d_csr[idx]]);
    #pragma unroll
    for (int o = 16; o; o >>= 1) acc += __shfl_xor_sync(0xffffffffu, acc, o);
    if (lane == 0)
        d_cs[node * DTOT + 96] = tanhf(d_dinv[node] * (d_G1[node] + acc) + b3[0]);
}

// ---------------- per-subgraph: sortpool + conv1 + pool + conv2 -> feat ----
__global__ __launch_bounds__(128) void k_sub(const float* __restrict__ w1,
                                             const float* __restrict__ b1,
                                             const float* __restrict__ w2,
                                             const float* __restrict__ b2) {
    __shared__ float key[MM];
    __shared__ int   sel[KTOP];
    __shared__ float xsm[KTOP][DTOT + 1];
    __shared__ float h1[C1][KTOP];
    __shared__ float pmax[C1][KTOP / 2];
    __shared__ float w1s[C1 * DTOT];
    __shared__ float w2s[C2 * C1 * 5];
    int sub = blockIdx.x;
    int tid = threadIdx.x;
    int base = sub * MM;

    for (int i = tid; i < C1 * DTOT; i += 128) w1s[i] = w1[i];
    for (int i = tid; i < C2 * C1 * 5; i += 128) w2s[i] = w2[i];
    if (tid < MM) key[tid] = d_cs[(base + tid) * DTOT + 96];
    __syncthreads();

    // stable top-K selection by rank (descending, earlier index wins ties)
    if (tid < MM) {
        float kv = key[tid];
        int r = 0;
        for (int m = 0; m < MM; m++) {
            float o = key[m];
            r += (o > kv) || (o == kv && m < tid);
        }
        if (r < KTOP) sel[r] = tid;
    }
    __syncthreads();

    for (int i = tid; i < KTOP * DTOT; i += 128) {
        int k = i / DTOT, d = i - k * DTOT;
        xsm[k][d] = d_cs[(base + sel[k]) * DTOT + d];
    }
    __syncthreads();

    // conv1: per-slot linear  h1[o][k] = relu(b1[o] + sum_d w1[o][d]*xs[k][d])
    for (int i = tid; i < C1 * KTOP; i += 128) {
        int o = i % C1, k = i / C1;
        float a = b1[o];
        #pragma unroll 4
        for (int d = 0; d < DTOT; d++) a += w1s[o * DTOT + d] * xsm[k][d];
        h1[o][k] = fmaxf(a, 0.f);
    }
    __syncthreads();

    // maxpool(2,2)
    for (int i = tid; i < C1 * (KTOP / 2); i += 128) {
        int o = i % C1, kk = i / C1;
        pmax[o][kk] = fmaxf(h1[o][2 * kk], h1[o][2 * kk + 1]);
    }
    __syncthreads();

    // conv2 (16->32, k=5, valid): 32 x 11 outputs, channel-major -> d_feat
    for (int i = tid; i < C2 * 11; i += 128) {
        int c = i / 11, l = i % 11;
        float a = b2[c];
        #pragma unroll
        for (int o = 0; o < C1; o++)
            #pragma unroll
            for (int t = 0; t < 5; t++)
                a += w2s[(c * C1 + o) * 5 + t] * pmax[o][l + t];
        d_feat[sub * L1IN + c * 11 + l] = fmaxf(a, 0.f);
    }
}

// ---------------- lin1 as tiled GEMM: [2048,352] @ [352,128] ---------------
__global__ __launch_bounds__(256) void k_lin1(const float* __restrict__ l1w,
                                              const float* __restrict__ l1b) {
    __shared__ float fs[16 * L1IN];      // 22.5 KB
    int tid = threadIdx.x;
    int row0 = blockIdx.x * 16;
    for (int i = tid; i < 16 * L1IN / 4; i += 256)
        ((float4*)fs)[i] = ((const float4*)(d_feat + row0 * L1IN))[i];
    __syncthreads();
    int tx = tid & 127, ty = tid >> 7;
    float acc[8] = {0.f, 0.f, 0.f, 0.f, 0.f, 0.f, 0.f, 0.f};
    for (int k = 0; k < L1IN; k++) {
        float w = __ldg(&l1w[k * HID + tx]);
        #pragma unroll
        for (int r = 0; r < 8; r++)
            acc[r] = fmaf(fs[(ty * 8 + r) * L1IN + k], w, acc[r]);
    }
    float bb = l1b[tx];
    #pragma unroll
    for (int r = 0; r < 8; r++)
        d_h3[(row0 + ty * 8 + r) * HID + tx] = acc[r] + bb;
}

// ---------------- final: mean -> relu -> lin2 -> log_softmax ---------------
__global__ __launch_bounds__(128) void k_final(const float* __restrict__ l2w,
                                               const float* __restrict__ l2b,
                                               float* __restrict__ out) {
    __shared__ float gr[HID];
    int g = blockIdx.x;
    int t = threadIdx.x;
    float s = 0.f;
    for (int u = 0; u < SSUB; u++) s += d_h3[(g * SSUB + u) * HID + t];
    gr[t] = fmaxf(s * (1.f / (float)SSUB), 0.f);
    __syncthreads();
    if (t < 32) {
        float val = 0.f;
        float o = -INFINITY;
        if (t < NCLS) {
            val = l2b[t];
            for (int j = 0; j < HID; j++)
                val = fmaf(gr[j], __ldg(&l2w[j * NCLS + t]), val);
            o = val;
        }
        float mx = o;
        #pragma unroll
        for (int sh = 16; sh; sh >>= 1)
            mx = fmaxf(mx, __shfl_xor_sync(0xffffffffu, mx, sh));
        float ex = (t < NCLS) ? expf(val - mx) : 0.f;
        #pragma unroll
        for (int sh = 16; sh; sh >>= 1)
            ex += __shfl_xor_sync(0xffffffffu, ex, sh);
        if (t < NCLS) out[g * NCLS + t] = val - mx - logf(ex);
    }
}

// ---------------- host launch ----------------------------------------------
extern "C" void kernel_launch(void* const* d_in, const int* in_sizes, int n_in,
                              void* d_out, int out_size) {
    const float *x = 0, *W0 = 0, *W1 = 0, *W2 = 0, *W3 = 0;
    const float *b0 = 0, *b1 = 0, *b2 = 0, *b3 = 0;
    const float *c1w = 0, *c1b = 0, *c2w = 0, *c2b = 0;
    const float *l1w = 0, *l1b = 0, *l2w = 0, *l2b = 0;
    const int* eidx = 0;
    int n1024 = 0, n32 = 0, n1 = 0;
    for (int i = 0; i < n_in; i++) {
        int sz = in_sizes[i];
        const void* p = d_in[i];
        switch (sz) {
            case 26214400: x = (const float*)p; break;
            case 6553600:  eidx = (const int*)p; break;
            case 8192:     W0 = (const float*)p; break;
            case 1024:     if (n1024++ == 0) W1 = (const float*)p; else W2 = (const float*)p; break;
            case 32: {
                int k = n32++;
                if (k == 0) b0 = (const float*)p;
                else if (k == 1) b1 = (const float*)p;
                else if (k == 2) b2 = (const float*)p;
                else if (k == 3) W3 = (const float*)p;
                else c2b = (const float*)p;
                break;
            }
            case 1:        if (n1++ == 0) b3 = (const float*)p; break;
            case 1552:     c1w = (const float*)p; break;
            case 16:       c1b = (const float*)p; break;
            case 2560:     c2w = (const float*)p; break;
            case 45056:    l1w = (const float*)p; break;
            case 128:      l1b = (const float*)p; break;
            case 1280:     l2w = (const float*)p; break;
            case 10:       l2b = (const float*)p; break;
            default: break;
        }
    }
    float* out = (float*)d_out;
    (void)out_size;

    // ---- graph preprocessing (CSR by destination; d_deg self-restoring) ----
    k_degree<<<EE / 4 / 256, 256>>>(eidx); // launch 1 (int4: 4 edges/thread)
    k_scan<<<1, 1024>>>();                 // launch 2: offsets + dinv
    k_fill<<<EE / 4 / 256, 256>>>(eidx);   // launch 3: csr, deg -> 0

    // ---- GCN stack (next-layer GEMM fused into aggregation) ----
    k_gemm0<<<NN / 128, 64>>>(x, W0);               // launch 4 (profiled)
    k_aggF<<<NN / 8, 256>>>(b0, 0, 0, W1);          // Ga->Gb, cs[:,0:32]
    k_aggF<<<NN / 8, 256>>>(b1, 32, 1, W2);         // Gb->Ga, cs[:,32:64]
    k_aggF2<<<NN / 8, 256>>>(b2, W3);               // Ga->G1, cs[:,64:96]
    k_agg1<<<NN / 8, 256>>>(b3);                    // cs[:,96]

    // ---- sortpool + convs -> feat ----
    k_sub<<<BGR * SSUB, 128>>>(c1w, c1b, c2w, c2b);

    // ---- lin1 GEMM ----
    k_lin1<<<BGR * SSUB / 16, 256>>>(l1w, l1b);

    // ---- mean -> relu -> lin2 -> log_softmax ----
    k_final<<<BGR, 128>>>(l2w, l2b, out);
}

// round 17
// speedup vs baseline: 1.0098x; 1.0098x over previous
#include <cuda_runtime.h>
#include <math.h>

// ---------------- problem constants (fixed by the dataset) ----------------
#define NN      102400      // B*S*M nodes
#define EE      3276800     // edges
#define FF      256         // input features
#define DTOT    97          // concat latent dim
#define BGR     64          // graphs
#define SSUB    32          // subgraphs per graph
#define MM      50          // nodes per subgraph
#define KTOP    30          // sort-pool k
#define C1      16
#define C2      32
#define L1IN    352
#define HID     128
#define NCLS    10

typedef unsigned long long ull;
__device__ __forceinline__ ull dup2(float a) {
    ull r; asm("mov.b64 %0,{%1,%1};" : "=l"(r) : "f"(a)); return r;
}
__device__ __forceinline__ ull fma2(ull a, ull b, ull c) {
    ull d; asm("fma.rn.f32x2 %0,%1,%2,%3;" : "=l"(d) : "l"(a), "l"(b), "l"(c)); return d;
}
__device__ __forceinline__ void upk(ull v, float& lo, float& hi) {
    asm("mov.b64 {%0,%1},%2;" : "=f"(lo), "=f"(hi) : "l"(v));
}

// ---------------- device scratch (static, no allocation) ------------------
// NOTE: never pass these symbols as kernel arguments from host code — that
// passes the host shadow address (silently readable-as-zeros on GB300 ATS).
// d_deg invariant: all-zeros at kernel_launch entry (module-load zeros it;
// k_fill's atomicSub cursor returns it to zero every call).
__device__ int   d_deg[NN];
__device__ float d_dinv[NN];
__device__ int   d_off[NN + 1];
__device__ int   d_csr[EE];
__device__ float d_Ga[NN * 32];
__device__ float d_Gb[NN * 32];
__device__ float d_G1[NN];           // layer-3 gemv output
__device__ float d_cs[NN * DTOT];    // concatenated states
__device__ float d_feat[BGR * SSUB * L1IN];
__device__ float d_h3[BGR * SSUB * HID];

// ---------------- preprocessing --------------------------------------------
__global__ void k_degree(const int* __restrict__ eidx) {
    int e = blockIdx.x * blockDim.x + threadIdx.x;
    if (e < EE) atomicAdd(&d_deg[eidx[EE + e]], 1);
}

// single-block coalesced scan: 100 tiles x 1024, warp-shuffle based.
// computes offsets + dinv. deg is left intact (k_fill consumes it to zero).
__global__ __launch_bounds__(1024) void k_scan() {
    __shared__ int wsum[32];
    int t = threadIdx.x, lane = t & 31, wid = t >> 5;
    int carry = 0;
    for (int tile = 0; tile < NN / 1024; tile++) {
        int idx = tile * 1024 + t;
        int v = d_deg[idx];
        int x = v;
        #pragma unroll
        for (int o = 1; o < 32; o <<= 1) {
            int y = __shfl_up_sync(0xffffffffu, x, o);
            if (lane >= o) x += y;
        }
        if (lane == 31) wsum[wid] = x;
        __syncthreads();
        if (wid == 0) {
            int s = wsum[lane];
            #pragma unroll
            for (int o = 1; o < 32; o <<= 1) {
                int y = __shfl_up_sync(0xffffffffu, s, o);
                if (lane >= o) s += y;
            }
            wsum[lane] = s;
        }
        __syncthreads();
        int off = carry + (wid ? wsum[wid - 1] : 0) + x - v;
        d_off[idx] = off;
        d_dinv[idx] = rsqrtf((float)(v + 1));  // +1 self loop
        carry += wsum[31];
        __syncthreads();
    }
    if (t == 1023) d_off[NN] = carry;
}

// fill with DOWN-counting cursor: after this kernel d_deg == 0 everywhere,
// restoring the entry invariant (no k_zero needed).
__global__ void k_fill(const int* __restrict__ eidx) {
    int e = blockIdx.x * blockDim.x + threadIdx.x;
    if (e < EE) {
        int c = eidx[EE + e];
        int p = d_off[c] + atomicSub(&d_deg[c], 1) - 1;
        d_csr[p] = eidx[e];
    }
}

// ---------------- GEMM layer 0: Ga = dinv * (x[N,256] @ W0[256,32]) --------
// 64 threads, tile 128 rows x 32 cols, per-thread 8 rows x 8 cols
// (best measured config: 52.0us). Packed fma.rn.f32x2 on row pairs;
// Xs transposed [kk][row] pitch 138 + 2-float skew per 32-row group;
// W cached in two 128-k halves (16KB). smem 33.7KB.
// per-accumulator k-order: k ascending 0..255 (identical numerics).
#define XPITCH 138
#define XIDX(kk, row) ((kk) * XPITCH + (row) + ((((row) >> 5)) << 1))
__global__ __launch_bounds__(64) void k_gemm0(const float* __restrict__ X,
                                              const float* __restrict__ W) {
    __shared__ float Ws[128 * 32];       // 16 KB: half of W ([kk][col])
    __shared__ float Xs[32 * XPITCH];    // 17.7 KB: [kk][row], skewed
    int tid = threadIdx.x;
    int node0 = blockIdx.x * 128;

    int ty = tid >> 2;       // 0..15 -> rows ty*8 .. ty*8+7
    int tx = tid & 3;        // cols tx*8 .. tx*8+7
    int xbase = ty * 8 + ((ty >> 2) << 1);   // skewed row base (const/thread)

    ull acc2[4][8];          // [row-pair][col]
    #pragma unroll
    for (int u = 0; u < 4; u++)
        #pragma unroll
        for (int c = 0; c < 8; c++) acc2[u][c] = 0ull;

    int q  = tid & 7;        // loader kk group: kk q*4..q*4+3
    int rr = tid >> 3;       // loader row residue 0..7

    for (int kh = 0; kh < 2; kh++) {
        __syncthreads();     // all compute on previous Ws done
        for (int i = tid; i < 1024; i += 64)
            ((float4*)Ws)[i] = ((const float4*)W)[kh * 1024 + i];
        for (int kt = 0; kt < 4; kt++) {
            __syncthreads();
            #pragma unroll
            for (int p = 0; p < 16; p++) {
                int row = p * 8 + rr;                // rows 0..127, each once
                float4 v = *(const float4*)
                    &X[(node0 + row) * FF + kh * 128 + kt * 32 + q * 4];
                Xs[XIDX(q * 4 + 0, row)] = v.x;
                Xs[XIDX(q * 4 + 1, row)] = v.y;
                Xs[XIDX(q * 4 + 2, row)] = v.z;
                Xs[XIDX(q * 4 + 3, row)] = v.w;
            }
            __syncthreads();
            #pragma unroll 8
            for (int kk = 0; kk < 32; kk++) {
                const float* wrow = &Ws[(kt * 32 + kk) * 32 + tx * 8];
                float4 w0 = *(const float4*)wrow;
                float4 w1 = *(const float4*)(wrow + 4);
                ull wd[8] = {dup2(w0.x), dup2(w0.y), dup2(w0.z), dup2(w0.w),
                             dup2(w1.x), dup2(w1.y), dup2(w1.z), dup2(w1.w)};
                const float* xrow = &Xs[kk * XPITCH + xbase];
                ull xp[4];
                xp[0] = *(const ull*)(xrow + 0);
                xp[1] = *(const ull*)(xrow + 2);
                xp[2] = *(const ull*)(xrow + 4);
                xp[3] = *(const ull*)(xrow + 6);
                #pragma unroll
                for (int u = 0; u < 4; u++)
                    #pragma unroll
                    for (int c = 0; c < 8; c++)
                        acc2[u][c] = fma2(xp[u], wd[c], acc2[u][c]);
            }
        }
    }
    #pragma unroll
    for (int u = 0; u < 4; u++) {
        int n0 = node0 + ty * 8 + 2 * u;
        float dv0 = d_dinv[n0], dv1 = d_dinv[n0 + 1];
        float lo[8], hi[8];
        #pragma unroll
        for (int c = 0; c < 8; c++) upk(acc2[u][c], lo[c], hi[c]);
        float4 a0 = {lo[0] * dv0, lo[1] * dv0, lo[2] * dv0, lo[3] * dv0};
        float4 a1 = {lo[4] * dv0, lo[5] * dv0, lo[6] * dv0, lo[7] * dv0};
        float4 b0 = {hi[0] * dv1, hi[1] * dv1, hi[2] * dv1, hi[3] * dv1};
        float4 b1 = {hi[4] * dv1, hi[5] * dv1, hi[6] * dv1, hi[7] * dv1};
        *(float4*)&d_Ga[n0 * 32 + tx * 8]           = a0;
        *(float4*)&d_Ga[n0 * 32 + tx * 8 + 4]       = a1;
        *(float4*)&d_Ga[(n0 + 1) * 32 + tx * 8]     = b0;
        *(float4*)&d_Ga[(n0 + 1) * 32 + tx * 8 + 4] = b1;
    }
}

// ---------------- vectorized gather: 4 neighbors per warp-instruction ------
// lane = g*8 + sub: group g (0..3) owns neighbors j = jj*4+g, sub (0..7)
// owns channel quad sub*4..sub*4+3. Per 4 edges: 1 SHFL + 1 LDG.128 + 4 FADD.
// Software-pipelined: batch n+1's csr indices are fetched BEFORE batch n's
// gathers, hiding the ~240cyc L2 latency of the csr row stream.
__device__ __forceinline__ float gather_row(const float* __restrict__ Gin,
                                            int warp, int lane) {
    const float4* __restrict__ Gin4 = (const float4*)Gin;
    int g = lane >> 3;
    int sub = lane & 7;
    float4 acc = make_float4(0.f, 0.f, 0.f, 0.f);
    if (g == 0) acc = __ldg(&Gin4[warp * 8 + sub]);     // self loop
    int s = d_off[warp], e = d_off[warp + 1];
    int idx0 = s + lane;
    int src = (idx0 < e) ? d_csr[idx0] : 0;             // batch 0 indices
    for (int base = s; base < e; base += 32) {
        int cnt = min(32, e - base);
        int nidx = base + 32 + lane;
        int nsrc = (nidx < e) ? d_csr[nidx] : 0;        // prefetch batch n+1
        #pragma unroll
        for (int jj = 0; jj < 8; jj++) {
            if (jj * 4 >= cnt) break;                   // warp-uniform
            int j = jj * 4 + g;
            int sj = __shfl_sync(0xffffffffu, src, j);
            if (j < cnt) {
                float4 v = __ldg(&Gin4[sj * 8 + sub]);
                acc.x += v.x; acc.y += v.y; acc.z += v.z; acc.w += v.w;
            }
        }
        src = nsrc;
    }
    // combine partial sums across the 4 groups (same sub)
    acc.x += __shfl_xor_sync(0xffffffffu, acc.x, 8);
    acc.y += __shfl_xor_sync(0xffffffffu, acc.y, 8);
    acc.z += __shfl_xor_sync(0xffffffffu, acc.z, 8);
    acc.w += __shfl_xor_sync(0xffffffffu, acc.w, 8);
    acc.x += __shfl_xor_sync(0xffffffffu, acc.x, 16);
    acc.y += __shfl_xor_sync(0xffffffffu, acc.y, 16);
    acc.z += __shfl_xor_sync(0xffffffffu, acc.z, 16);
    acc.w += __shfl_xor_sync(0xffffffffu, acc.w, 16);
    // redistribute: lane k takes component k&3 from lane k>>2 (sub = k>>2)
    int srcl = lane >> 2;
    float c0 = __shfl_sync(0xffffffffu, acc.x, srcl);
    float c1 = __shfl_sync(0xffffffffu, acc.y, srcl);
    float c2 = __shfl_sync(0xffffffffu, acc.z, srcl);
    float c3 = __shfl_sync(0xffffffffu, acc.w, srcl);
    int r = lane & 3;
    return (r == 0) ? c0 : (r == 1) ? c1 : (r == 2) ? c2 : c3;
}

// ---------------- fused aggregation + next-layer 32x32 GEMM ----------------
// ab=0: Gin=d_Ga, Gout=d_Gb;  ab=1: Gin=d_Gb, Gout=d_Ga (device-side select).
__global__ __launch_bounds__(256) void k_aggF(const float* __restrict__ b,
                                              int colOff, int ab,
                                              const float* __restrict__ Wn) {
    const float* __restrict__ Gin = ab ? d_Gb : d_Ga;
    float* __restrict__ Gout = ab ? d_Ga : d_Gb;
    __shared__ float Ws[1024];
    int tid = threadIdx.x;
    if (tid < 256) ((float4*)Ws)[tid] = ((const float4*)Wn)[tid];
    __syncthreads();

    int warp = (blockIdx.x * 256 + tid) >> 5;
    int lane = tid & 31;
    float acc = gather_row(Gin, warp, lane);
    float dv = d_dinv[warp];
    float v = tanhf(dv * acc + b[lane]);
    d_cs[warp * DTOT + colOff + lane] = v;
    float g = 0.f;
    #pragma unroll
    for (int k = 0; k < 32; k++) {
        float vk = __shfl_sync(0xffffffffu, v, k);
        g = fmaf(vk, Ws[k * 32 + lane], g);
    }
    Gout[warp * 32 + lane] = g * dv;
}

// layer-2 variant: fused agg (Gin = d_Ga) + gemv(32->1) -> d_G1
__global__ __launch_bounds__(256) void k_aggF2(const float* __restrict__ b,
                                               const float* __restrict__ W3) {
    int tid = threadIdx.x;
    int warp = (blockIdx.x * 256 + tid) >> 5;
    int lane = tid & 31;
    float acc = gather_row(d_Ga, warp, lane);
    float dv = d_dinv[warp];
    float v = tanhf(dv * acc + b[lane]);
    d_cs[warp * DTOT + 64 + lane] = v;
    float t = v * __ldg(&W3[lane]);
    #pragma unroll
    for (int o = 16; o; o >>= 1) t += __shfl_xor_sync(0xffffffffu, t, o);
    if (lane == 0) d_G1[warp] = t * dv;
}

__global__ __launch_bounds__(256) void k_agg1(const float* __restrict__ b3) {
    int node = (blockIdx.x * blockDim.x + threadIdx.x) >> 5;
    int lane = threadIdx.x & 31;
    int s = d_off[node], e = d_off[node + 1];
    float acc = 0.f;
    for (int idx = s + lane; idx < e; idx += 32)
        acc += __ldg(&d_G1[d_csr[idx]]);
    #pragma unroll
    for (int o = 16; o; o >>= 1) acc += __shfl_xor_sync(0xffffffffu, acc, o);
    if (lane == 0)
        d_cs[node * DTOT + 96] = tanhf(d_dinv[node] * (d_G1[node] + acc) + b3[0]);
}

// ---------------- per-subgraph: sortpool + conv1 + pool + conv2 -> feat ----
__global__ __launch_bounds__(128) void k_sub(const float* __restrict__ w1,
                                             const float* __restrict__ b1,
                                             const float* __restrict__ w2,
                                             const float* __restrict__ b2) {
    __shared__ float key[MM];
    __shared__ int   sel[KTOP];
    __shared__ float xsm[KTOP][DTOT + 1];
    __shared__ float h1[C1][KTOP];
    __shared__ float pmax[C1][KTOP / 2];
    __shared__ float w1s[C1 * DTOT];
    __shared__ float w2s[C2 * C1 * 5];
    int sub = blockIdx.x;
    int tid = threadIdx.x;
    int base = sub * MM;

    for (int i = tid; i < C1 * DTOT; i += 128) w1s[i] = w1[i];
    for (int i = tid; i < C2 * C1 * 5; i += 128) w2s[i] = w2[i];
    if (tid < MM) key[tid] = d_cs[(base + tid) * DTOT + 96];
    __syncthreads();

    // stable top-K selection by rank (descending, earlier index wins ties)
    if (tid < MM) {
        float kv = key[tid];
        int r = 0;
        for (int m = 0; m < MM; m++) {
            float o = key[m];
            r += (o > kv) || (o == kv && m < tid);
        }
        if (r < KTOP) sel[r] = tid;
    }
    __syncthreads();

    for (int i = tid; i < KTOP * DTOT; i += 128) {
        int k = i / DTOT, d = i - k * DTOT;
        xsm[k][d] = d_cs[(base + sel[k]) * DTOT + d];
    }
    __syncthreads();

    // conv1: per-slot linear  h1[o][k] = relu(b1[o] + sum_d w1[o][d]*xs[k][d])
    for (int i = tid; i < C1 * KTOP; i += 128) {
        int o = i % C1, k = i / C1;
        float a = b1[o];
        #pragma unroll 4
        for (int d = 0; d < DTOT; d++) a += w1s[o * DTOT + d] * xsm[k][d];
        h1[o][k] = fmaxf(a, 0.f);
    }
    __syncthreads();

    // maxpool(2,2)
    for (int i = tid; i < C1 * (KTOP / 2); i += 128) {
        int o = i % C1, kk = i / C1;
        pmax[o][kk] = fmaxf(h1[o][2 * kk], h1[o][2 * kk + 1]);
    }
    __syncthreads();

    // conv2 (16->32, k=5, valid): 32 x 11 outputs, channel-major -> d_feat
    for (int i = tid; i < C2 * 11; i += 128) {
        int c = i / 11, l = i % 11;
        float a = b2[c];
        #pragma unroll
        for (int o = 0; o < C1; o++)
            #pragma unroll
            for (int t = 0; t < 5; t++)
                a += w2s[(c * C1 + o) * 5 + t] * pmax[o][l + t];
        d_feat[sub * L1IN + c * 11 + l] = fmaxf(a, 0.f);
    }
}

// ---------------- lin1 as tiled GEMM: [2048,352] @ [352,128] ---------------
__global__ __launch_bounds__(256) void k_lin1(const float* __restrict__ l1w,
                                              const float* __restrict__ l1b) {
    __shared__ float fs[16 * L1IN];      // 22.5 KB
    int tid = threadIdx.x;
    int row0 = blockIdx.x * 16;
    for (int i = tid; i < 16 * L1IN / 4; i += 256)
        ((float4*)fs)[i] = ((const float4*)(d_feat + row0 * L1IN))[i];
    __syncthreads();
    int tx = tid & 127, ty = tid >> 7;
    float acc[8] = {0.f, 0.f, 0.f, 0.f, 0.f, 0.f, 0.f, 0.f};
    for (int k = 0; k < L1IN; k++) {
        float w = __ldg(&l1w[k * HID + tx]);
        #pragma unroll
        for (int r = 0; r < 8; r++)
            acc[r] = fmaf(fs[(ty * 8 + r) * L1IN + k], w, acc[r]);
    }
    float bb = l1b[tx];
    #pragma unroll
    for (int r = 0; r < 8; r++)
        d_h3[(row0 + ty * 8 + r) * HID + tx] = acc[r] + bb;
}

// ---------------- final: mean -> relu -> lin2 -> log_softmax ---------------
__global__ __launch_bounds__(128) void k_final(const float* __restrict__ l2w,
                                               const float* __restrict__ l2b,
                                               float* __restrict__ out) {
    __shared__ float gr[HID];
    int g = blockIdx.x;
    int t = threadIdx.x;
    float s = 0.f;
    for (int u = 0; u < SSUB; u++) s += d_h3[(g * SSUB + u) * HID + t];
    gr[t] = fmaxf(s * (1.f / (float)SSUB), 0.f);
    __syncthreads();
    if (t < 32) {
        float val = 0.f;
        float o = -INFINITY;
        if (t < NCLS) {
            val = l2b[t];
            for (int j = 0; j < HID; j++)
                val = fmaf(gr[j], __ldg(&l2w[j * NCLS + t]), val);
            o = val;
        }
        float mx = o;
        #pragma unroll
        for (int sh = 16; sh; sh >>= 1)
            mx = fmaxf(mx, __shfl_xor_sync(0xffffffffu, mx, sh));
        float ex = (t < NCLS) ? expf(val - mx) : 0.f;
        #pragma unroll
        for (int sh = 16; sh; sh >>= 1)
            ex += __shfl_xor_sync(0xffffffffu, ex, sh);
        if (t < NCLS) out[g * NCLS + t] = val - mx - logf(ex);
    }
}

// ---------------- host launch ----------------------------------------------
extern "C" void kernel_launch(void* const* d_in, const int* in_sizes, int n_in,
                              void* d_out, int out_size) {
    const float *x = 0, *W0 = 0, *W1 = 0, *W2 = 0, *W3 = 0;
    const float *b0 = 0, *b1 = 0, *b2 = 0, *b3 = 0;
    const float *c1w = 0, *c1b = 0, *c2w = 0, *c2b = 0;
    const float *l1w = 0, *l1b = 0, *l2w = 0, *l2b = 0;
    const int* eidx = 0;
    int n1024 = 0, n32 = 0, n1 = 0;
    for (int i = 0; i < n_in; i++) {
        int sz = in_sizes[i];
        const void* p = d_in[i];
        switch (sz) {
            case 26214400: x = (const float*)p; break;
            case 6553600:  eidx = (const int*)p; break;
            case 8192:     W0 = (const float*)p; break;
            case 1024:     if (n1024++ == 0) W1 = (const float*)p; else W2 = (const float*)p; break;
            case 32: {
                int k = n32++;
                if (k == 0) b0 = (const float*)p;
                else if (k == 1) b1 = (const float*)p;
                else if (k == 2) b2 = (const float*)p;
                else if (k == 3) W3 = (const float*)p;
                else c2b = (const float*)p;
                break;
            }
            case 1:        if (n1++ == 0) b3 = (const float*)p; break;
            case 1552:     c1w = (const float*)p; break;
            case 16:       c1b = (const float*)p; break;
            case 2560:     c2w = (const float*)p; break;
            case 45056:    l1w = (const float*)p; break;
            case 128:      l1b = (const float*)p; break;
            case 1280:     l2w = (const float*)p; break;
            case 10:       l2b = (const float*)p; break;
            default: break;
        }
    }
    float* out = (float*)d_out;
    (void)out_size;

    // ---- graph preprocessing (CSR by destination; d_deg self-restoring) ----
    k_degree<<<EE / 512, 512>>>(eidx);     // launch 1
    k_scan<<<1, 1024>>>();                 // launch 2: offsets + dinv
    k_fill<<<EE / 512, 512>>>(eidx);       // launch 3: csr, deg -> 0

    // ---- GCN stack (next-layer GEMM fused into aggregation) ----
    k_gemm0<<<NN / 128, 64>>>(x, W0);               // launch 4 (profiled)
    k_aggF<<<NN / 8, 256>>>(b0, 0, 0, W1);          // Ga->Gb, cs[:,0:32]
    k_aggF<<<NN / 8, 256>>>(b1, 32, 1, W2);         // Gb->Ga, cs[:,32:64]
    k_aggF2<<<NN / 8, 256>>>(b2, W3);               // Ga->G1, cs[:,64:96]
    k_agg1<<<NN / 8, 256>>>(b3);                    // cs[:,96]

    // ---- sortpool + convs -> feat ----
    k_sub<<<BGR * SSUB, 128>>>(c1w, c1b, c2w, c2b);

    // ---- lin1 GEMM ----
    k_lin1<<<BGR * SSUB / 16, 256>>>(l1w, l1b);

    // ---- mean -> relu -> lin2 -> log_softmax ----
    k_final<<<BGR, 128>>>(l2w, l2b, out);
}